// round 4
// baseline (speedup 1.0000x reference)
#include <cuda_runtime.h>
#include <cstdint>
#include <cstddef>
#include <math.h>

// ---------------------------------------------------------------------------
// Problem constants
// ---------------------------------------------------------------------------
#define BB   8       // batch
#define NF   4096    // N_FULL
#define NL   1024    // N_LAT
#define CC   256     // channels
#define HH   8       // heads
#define VD   32      // C / H

// ---------------------------------------------------------------------------
// Scratch layout (single __device__ array; no allocations allowed)
// ---------------------------------------------------------------------------
// att (big, reused for down & up):  H*NL*NF            = 33,554,432
// att_p (latent blocks):            H*NL*NL            =  8,388,608
// val:                              B*NF*CC            =  8,388,608
// h_full:                           B*NF*CC            =  8,388,608
// tmp_full:                         B*NF*CC            =  8,388,608
// lat0, lat1, lat2:                 B*NL*CC each       =  2,097,152 * 3
// wrep:                             CC*CC              =     65,536
static const size_t OFF_ATT     = 0;
static const size_t OFF_ATT_P   = OFF_ATT     + (size_t)HH*NL*NF;
static const size_t OFF_VAL     = OFF_ATT_P   + (size_t)HH*NL*NL;
static const size_t OFF_HFULL   = OFF_VAL     + (size_t)BB*NF*CC;
static const size_t OFF_TMPFULL = OFF_HFULL   + (size_t)BB*NF*CC;
static const size_t OFF_LAT0    = OFF_TMPFULL + (size_t)BB*NF*CC;
static const size_t OFF_LAT1    = OFF_LAT0    + (size_t)BB*NL*CC;
static const size_t OFF_LAT2    = OFF_LAT1    + (size_t)BB*NL*CC;
static const size_t OFF_WREP    = OFF_LAT2    + (size_t)BB*NL*CC;
static const size_t SCRATCH_ELEMS = OFF_WREP + (size_t)CC*CC;

__device__ float g_scratch[SCRATCH_ELEMS];

// ---------------------------------------------------------------------------
// Device helpers
// ---------------------------------------------------------------------------
__device__ __forceinline__ float gelu_tanh(float x) {
    // jax.nn.gelu default (approximate=True):
    // 0.5*x*(1+tanh(sqrt(2/pi)*(x+0.044715*x^3)))
    const float k0 = 0.7978845608028654f;
    const float k1 = 0.044715f;
    float x3 = x * x * x;
    float t  = tanhf(k0 * (x + k1 * x3));
    return 0.5f * x * (1.0f + t);
}

__device__ __forceinline__ float head_scale(float rv) {
    // JAX: tan(0.25*pi*(1-1e-7) * (1+sin(r))), all fp32 on-array ops.
    const float c = (float)(0.25 * 3.14159265358979323846 * (1.0 - 1e-7));
    float s = sinf(rv);
    return tanf(c * (1.0f + s));
}

// ---------------------------------------------------------------------------
// Encoder: h[b,n,c] = gelu(sum_{j<4} x[b,n,j]*W[j,c] + b[c])
// ---------------------------------------------------------------------------
__global__ void k_encoder(const float* __restrict__ x,
                          const float* __restrict__ w,
                          const float* __restrict__ bias,
                          float* __restrict__ out) {
    int idx = blockIdx.x * blockDim.x + threadIdx.x;   // total = B*NF*CC
    int m = idx >> 8;
    int c = idx & 255;
    const float* xr = x + (size_t)m * 4;
    float acc = bias[c];
    acc += xr[0] * w[c] + xr[1] * w[256 + c] + xr[2] * w[512 + c] + xr[3] * w[768 + c];
    out[idx] = gelu_tanh(acc);
}

// ---------------------------------------------------------------------------
// Repack head weights [H, C, VD] -> [C, H*VD] row-major
// ---------------------------------------------------------------------------
__global__ void k_repack_w(const float* __restrict__ w_hcv, float* __restrict__ wrep) {
    int idx = blockIdx.x * blockDim.x + threadIdx.x;   // 65536
    int k = idx >> 8;
    int n = idx & 255;
    int h = n >> 5;
    int v = n & 31;
    wrep[idx] = w_hcv[(size_t)h * CC * VD + (size_t)k * VD + v];
}

// ---------------------------------------------------------------------------
// Global (unmasked) attention rows: att = softmax(-md*scale) per (h,q) row.
// One block per row. Dynamic smem: Nk floats (row) + 256 floats (reduce).
// ---------------------------------------------------------------------------
__global__ void k_att_global(const float* __restrict__ md,
                             const float* __restrict__ r,
                             float* __restrict__ att,
                             int Nq, int Nk) {
    extern __shared__ float sm[];
    float* row = sm;
    float* red = sm + Nk;
    int rowid = blockIdx.x;
    int h = rowid / Nq;
    float scale = head_scale(r[h]);
    const float* src = md + (size_t)rowid * Nk;
    float* dst = att + (size_t)rowid * Nk;
    int tid = threadIdx.x;

    float mn = 3.402823466e+38f;
    for (int k = tid; k < Nk; k += 256) {
        float v = src[k] * scale;
        row[k] = v;
        mn = fminf(mn, v);
    }
    red[tid] = mn; __syncthreads();
    for (int s = 128; s > 0; s >>= 1) {
        if (tid < s) red[tid] = fminf(red[tid], red[tid + s]);
        __syncthreads();
    }
    mn = red[0];
    __syncthreads();

    float sum = 0.0f;
    for (int k = tid; k < Nk; k += 256) {
        float e = expf(mn - row[k]);   // logits = -sd; max logit = -mn
        row[k] = e;
        sum += e;
    }
    red[tid] = sum; __syncthreads();
    for (int s = 128; s > 0; s >>= 1) {
        if (tid < s) red[tid] += red[tid + s];
        __syncthreads();
    }
    float inv = 1.0f / red[0];
    for (int k = tid; k < Nk; k += 256) dst[k] = row[k] * inv;
}

// ---------------------------------------------------------------------------
// Masked attention rows (locality=30, Nk=1024):
//  sd = md*scale; thr = percentile30 (linear interp at idx 306.9);
//  att = softmax(-sd) over entries sd <= thr, 0 elsewhere.
// One block (256 threads) per row; bitonic full sort of a copy in smem.
// ---------------------------------------------------------------------------
__global__ void k_att_masked(const float* __restrict__ md,
                             const float* __restrict__ r,
                             float* __restrict__ att) {
    __shared__ float vals[NL];
    __shared__ float srt[NL];
    __shared__ float red[256];
    int rowid = blockIdx.x;           // h*NL + q
    int h = rowid / NL;
    float scale = head_scale(r[h]);
    const float* src = md + (size_t)rowid * NL;
    float* dst = att + (size_t)rowid * NL;
    int tid = threadIdx.x;

    for (int k = tid; k < NL; k += 256) {
        float v = src[k] * scale;
        vals[k] = v;
        srt[k]  = v;
    }
    __syncthreads();

    // Bitonic sort ascending (1024 elements)
    for (int k = 2; k <= NL; k <<= 1) {
        for (int j = k >> 1; j > 0; j >>= 1) {
            for (int i = tid; i < NL; i += 256) {
                int ixj = i ^ j;
                if (ixj > i) {
                    bool up = ((i & k) == 0);
                    float a = srt[i], b = srt[ixj];
                    if ((a > b) == up) { srt[i] = b; srt[ixj] = a; }
                }
            }
            __syncthreads();
        }
    }

    // percentile(30) over n=1024: idx = 0.3*1023 = 306.9
    float a306 = srt[306], a307 = srt[307];
    float thr = a306 + 0.9f * (a307 - a306);
    float mn  = srt[0];   // global min is always kept

    float sum = 0.0f;
    for (int k = tid; k < NL; k += 256) {
        float v = vals[k];
        float e = (v <= thr) ? expf(mn - v) : 0.0f;
        vals[k] = e;
        sum += e;
    }
    red[tid] = sum; __syncthreads();
    for (int s = 128; s > 0; s >>= 1) {
        if (tid < s) red[tid] += red[tid + s];
        __syncthreads();
    }
    float inv = 1.0f / red[0];
    for (int k = tid; k < NL; k += 256) dst[k] = vals[k] * inv;
}

// ---------------------------------------------------------------------------
// Generic SGEMM: C = epilogue(A[M,K] @ B[K,256])
//   - grid: (M/64, 4, nHeads); blockIdx.z offsets A/B by per-head strides
//   - flags: bit0 = gelu, bit1 = add addbuf[m*256+n]
//   - store_mode: 0 plain C[m*256+n]
//                 1 att-apply scatter: col n=(b,v) -> C[b*s*256 + m*256 + h*32 + v]
//                 2 value scatter: row m=(b,kpos) -> C[hh*s*256 + kpos*256 + b*32 + vv]
// M % 64 == 0, K % 16 == 0 for all call sites (1024/4096/8192/32768; 256/1024/4096).
// ---------------------------------------------------------------------------
__global__ void __launch_bounds__(256)
k_gemm(const float* __restrict__ A, const float* __restrict__ B,
       float* __restrict__ C,
       int M, int K,
       size_t strideA_h, size_t strideB_h,
       const float* __restrict__ bias,
       const float* __restrict__ addbuf,
       int flags, int store_mode, int s_param) {
    const int h = blockIdx.z;
    A += (size_t)h * strideA_h;
    B += (size_t)h * strideB_h;

    __shared__ float As[16][65];
    __shared__ float Bs[16][68];

    const int m0 = blockIdx.x * 64;
    const int n0 = blockIdx.y * 64;
    const int tid = threadIdx.x;
    const int tx = tid & 15;
    const int ty = tid >> 4;

    float acc[4][4];
#pragma unroll
    for (int i = 0; i < 4; i++)
#pragma unroll
        for (int j = 0; j < 4; j++) acc[i][j] = 0.0f;

    for (int k0 = 0; k0 < K; k0 += 16) {
        // load A tile 64x16 (transposed into smem)
        {
            int kk = tid & 15;
            int mm = tid >> 4;
#pragma unroll
            for (int rr = 0; rr < 4; rr++) {
                int m = m0 + mm + rr * 16;
                As[kk][mm + rr * 16] = A[(size_t)m * K + k0 + kk];
            }
        }
        // load B tile 16x64
        {
            int nn = tid & 63;
            int kk = tid >> 6;
#pragma unroll
            for (int rr = 0; rr < 4; rr++) {
                Bs[kk + rr * 4][nn] = B[(size_t)(k0 + kk + rr * 4) * 256 + n0 + nn];
            }
        }
        __syncthreads();
#pragma unroll
        for (int kk = 0; kk < 16; kk++) {
            float a[4], b[4];
#pragma unroll
            for (int i = 0; i < 4; i++) a[i] = As[kk][ty * 4 + i];
#pragma unroll
            for (int j = 0; j < 4; j++) b[j] = Bs[kk][tx * 4 + j];
#pragma unroll
            for (int i = 0; i < 4; i++)
#pragma unroll
                for (int j = 0; j < 4; j++) acc[i][j] += a[i] * b[j];
        }
        __syncthreads();
    }

#pragma unroll
    for (int i = 0; i < 4; i++) {
        int m = m0 + ty * 4 + i;
#pragma unroll
        for (int j = 0; j < 4; j++) {
            int n = n0 + tx * 4 + j;
            float v = acc[i][j];
            if (bias) v += bias[n];
            if (flags & 2) v += addbuf[(size_t)m * 256 + n];
            if (flags & 1) v = gelu_tanh(v);
            size_t idx;
            if (store_mode == 0) {
                idx = (size_t)m * 256 + n;
            } else if (store_mode == 1) {
                int bb = n >> 5, vv = n & 31;
                idx = (size_t)bb * s_param * 256 + (size_t)m * 256 + (size_t)h * 32 + vv;
            } else {
                int bb = m / s_param, kp = m % s_param;
                int hh = n >> 5, vv = n & 31;
                idx = (size_t)hh * s_param * 256 + (size_t)kp * 256 + (size_t)bb * 32 + vv;
            }
            C[idx] = v;
        }
    }
}

// ---------------------------------------------------------------------------
// Final projection: out[m] = A[m,:] . w[:,0] + b[0]   (one warp per row)
// ---------------------------------------------------------------------------
__global__ void k_fc2(const float* __restrict__ A, const float* __restrict__ w,
                      const float* __restrict__ b, float* __restrict__ out, int M) {
    int gwarp = (blockIdx.x * blockDim.x + threadIdx.x) >> 5;
    int lane = threadIdx.x & 31;
    if (gwarp >= M) return;
    const float* a = A + (size_t)gwarp * 256;
    float s = 0.0f;
#pragma unroll
    for (int k = lane; k < 256; k += 32) s += a[k] * w[k];
#pragma unroll
    for (int off = 16; off > 0; off >>= 1)
        s += __shfl_down_sync(0xFFFFFFFFu, s, off);
    if (lane == 0) out[gwarp] = s + b[0];
}

// ---------------------------------------------------------------------------
// Host orchestration
// ---------------------------------------------------------------------------
extern "C" void kernel_launch(void* const* d_in, const int* in_sizes, int n_in,
                              void* d_out, int out_size) {
    (void)in_sizes; (void)n_in; (void)out_size;

    const float* x       = (const float*)d_in[0];
    const float* md_down = (const float*)d_in[1];
    const float* md_p[2] = {(const float*)d_in[2], (const float*)d_in[3]};
    const float* md_up   = (const float*)d_in[4];
    const float* en_w    = (const float*)d_in[5];
    const float* en_b    = (const float*)d_in[6];
    const float* down_r  = (const float*)d_in[7];
    const float* down_w  = (const float*)d_in[8];
    const float* pa_r[2] = {(const float*)d_in[9],  (const float*)d_in[17]};
    const float* pa_w[2] = {(const float*)d_in[10], (const float*)d_in[18]};
    const float* f1w[2]  = {(const float*)d_in[11], (const float*)d_in[19]};
    const float* f1b[2]  = {(const float*)d_in[12], (const float*)d_in[20]};
    const float* f2w[2]  = {(const float*)d_in[13], (const float*)d_in[21]};
    const float* f2b[2]  = {(const float*)d_in[14], (const float*)d_in[22]};
    const float* rw[2]   = {(const float*)d_in[15], (const float*)d_in[23]};
    const float* rb[2]   = {(const float*)d_in[16], (const float*)d_in[24]};
    const float* up_r    = (const float*)d_in[25];
    const float* up_w    = (const float*)d_in[26];
    const float* de1w    = (const float*)d_in[27];
    const float* de1b    = (const float*)d_in[28];
    const float* de2w    = (const float*)d_in[29];
    const float* de2b    = (const float*)d_in[30];

    float* S = nullptr;
    cudaGetSymbolAddress((void**)&S, g_scratch);
    float* att     = S + OFF_ATT;
    float* attp    = S + OFF_ATT_P;
    float* val     = S + OFF_VAL;
    float* hfull   = S + OFF_HFULL;
    float* tmpfull = S + OFF_TMPFULL;
    float* lat0    = S + OFF_LAT0;
    float* lat1    = S + OFF_LAT1;
    float* lat2    = S + OFF_LAT2;
    float* wrep    = S + OFF_WREP;

    // ---- encoder ----
    k_encoder<<<(BB * NF * CC) / 256, 256>>>(x, en_w, en_b, hfull);

    // ---- down attention (global, Nq=1024, Nk=4096) ----
    k_repack_w<<<256, 256>>>(down_w, wrep);
    k_gemm<<<dim3(BB * NF / 64, 4, 1), 256>>>(hfull, wrep, val, BB * NF, 256,
                                              0, 0, nullptr, nullptr, 0, 2, NF);
    k_att_global<<<HH * NL, 256, (NF + 256) * sizeof(float)>>>(md_down, down_r, att, NL, NF);
    k_gemm<<<dim3(NL / 64, 4, HH), 256>>>(att, val, lat0, NL, NF,
                                          (size_t)NL * NF, (size_t)NF * CC,
                                          nullptr, nullptr, 1, 1, NL);

    // ---- two latent PiT blocks (masked attention, locality=30) ----
    float* hin  = lat0;
    float* bufP = lat1;
    float* bufT = lat2;
    for (int i = 0; i < 2; i++) {
        k_repack_w<<<256, 256>>>(pa_w[i], wrep);
        k_gemm<<<dim3(BB * NL / 64, 4, 1), 256>>>(hin, wrep, val, BB * NL, 256,
                                                  0, 0, nullptr, nullptr, 0, 2, NL);
        k_att_masked<<<HH * NL, 256>>>(md_p[i], pa_r[i], attp);
        k_gemm<<<dim3(NL / 64, 4, HH), 256>>>(attp, val, bufP, NL, NL,
                                              (size_t)NL * NL, (size_t)NL * CC,
                                              nullptr, nullptr, 1, 1, NL);
        // mlp fc1 (gelu)
        k_gemm<<<dim3(BB * NL / 64, 4, 1), 256>>>(bufP, f1w[i], bufT, BB * NL, 256,
                                                  0, 0, f1b[i], nullptr, 1, 0, 0);
        // mlp fc2 (no act) -> overwrite bufP
        k_gemm<<<dim3(BB * NL / 64, 4, 1), 256>>>(bufT, f2w[i], bufP, BB * NL, 256,
                                                  0, 0, f2b[i], nullptr, 0, 0, 0);
        // h = gelu(mlp + hin@rw + rb) -> bufT
        k_gemm<<<dim3(BB * NL / 64, 4, 1), 256>>>(hin, rw[i], bufT, BB * NL, 256,
                                                  0, 0, rb[i], bufP, 3, 0, 0);
        float* nh = bufT; bufT = hin; hin = nh;
    }

    // ---- up attention (global, Nq=4096, Nk=1024) ----
    k_repack_w<<<256, 256>>>(up_w, wrep);
    k_gemm<<<dim3(BB * NL / 64, 4, 1), 256>>>(hin, wrep, val, BB * NL, 256,
                                              0, 0, nullptr, nullptr, 0, 2, NL);
    k_att_global<<<HH * NF, 256, (NL + 256) * sizeof(float)>>>(md_up, up_r, att, NF, NL);
    k_gemm<<<dim3(NF / 64, 4, HH), 256>>>(att, val, hfull, NF, NL,
                                          (size_t)NF * NL, (size_t)NL * CC,
                                          nullptr, nullptr, 1, 1, NF);

    // ---- decoder ----
    k_gemm<<<dim3(BB * NF / 64, 4, 1), 256>>>(hfull, de1w, tmpfull, BB * NF, 256,
                                              0, 0, de1b, nullptr, 1, 0, 0);
    k_fc2<<<(BB * NF * 32) / 256, 256>>>(tmpfull, de2w, de2b, (float*)d_out, BB * NF);
}

// round 7
// speedup vs baseline: 1.7242x; 1.7242x over previous
#include <cuda_runtime.h>
#include <cstdint>
#include <cstddef>
#include <math.h>

// ---------------------------------------------------------------------------
// Problem constants
// ---------------------------------------------------------------------------
#define BB   8       // batch
#define NF   4096    // N_FULL
#define NL   1024    // N_LAT
#define CC   256     // channels
#define HH   8       // heads
#define VD   32      // C / H

// ---------------------------------------------------------------------------
// Scratch layout (single __device__ array; no allocations allowed)
// ---------------------------------------------------------------------------
static const size_t OFF_ATT     = 0;
static const size_t OFF_ATT_P   = OFF_ATT     + (size_t)HH*NL*NF;
static const size_t OFF_VAL     = OFF_ATT_P   + (size_t)HH*NL*NL;
static const size_t OFF_HFULL   = OFF_VAL     + (size_t)BB*NF*CC;
static const size_t OFF_TMPFULL = OFF_HFULL   + (size_t)BB*NF*CC;
static const size_t OFF_LAT0    = OFF_TMPFULL + (size_t)BB*NF*CC;
static const size_t OFF_LAT1    = OFF_LAT0    + (size_t)BB*NL*CC;
static const size_t OFF_LAT2    = OFF_LAT1    + (size_t)BB*NL*CC;
static const size_t OFF_WREP    = OFF_LAT2    + (size_t)BB*NL*CC;
static const size_t SCRATCH_ELEMS = OFF_WREP + (size_t)CC*CC;

__device__ float g_scratch[SCRATCH_ELEMS];

// Dynamic smem footprint of the TF32 GEMM:
//   As: 2*2*8*128 u32 = 8192 words  (32768 B)
//   Bs: 2*2*16*66 u32 = 4224 words  (16896 B)
#define GEMM_SMEM_WORDS_A (2*2*8*128)
#define GEMM_SMEM_WORDS_B (2*2*16*66)
#define GEMM_SMEM_BYTES   ((GEMM_SMEM_WORDS_A + GEMM_SMEM_WORDS_B) * 4)

// ---------------------------------------------------------------------------
// Device helpers
// ---------------------------------------------------------------------------
__device__ __forceinline__ float gelu_tanh(float x) {
    const float k0 = 0.7978845608028654f;
    const float k1 = 0.044715f;
    float x3 = x * x * x;
    float t  = tanhf(k0 * (x + k1 * x3));
    return 0.5f * x * (1.0f + t);
}

__device__ __forceinline__ float head_scale(float rv) {
    const float c = (float)(0.25 * 3.14159265358979323846 * (1.0 - 1e-7));
    float s = sinf(rv);
    return tanf(c * (1.0f + s));
}

__device__ __forceinline__ uint32_t f2tf32(float f) {
    uint32_t u;
    asm("cvt.rna.tf32.f32 %0, %1;" : "=r"(u) : "f"(f));
    return u;
}

__device__ __forceinline__ void mma_tf32(float* d, const uint32_t* a, const uint32_t* b) {
    asm volatile(
        "mma.sync.aligned.m16n8k8.row.col.f32.tf32.tf32.f32 "
        "{%0,%1,%2,%3}, {%4,%5,%6,%7}, {%8,%9}, {%0,%1,%2,%3};"
        : "+f"(d[0]), "+f"(d[1]), "+f"(d[2]), "+f"(d[3])
        : "r"(a[0]), "r"(a[1]), "r"(a[2]), "r"(a[3]), "r"(b[0]), "r"(b[1]));
}

// ---------------------------------------------------------------------------
// Encoder: h[b,n,c] = gelu(sum_{j<4} x[b,n,j]*W[j,c] + b[c])
// ---------------------------------------------------------------------------
__global__ void k_encoder(const float* __restrict__ x,
                          const float* __restrict__ w,
                          const float* __restrict__ bias,
                          float* __restrict__ out) {
    int idx = blockIdx.x * blockDim.x + threadIdx.x;   // total = B*NF*CC
    int m = idx >> 8;
    int c = idx & 255;
    const float* xr = x + (size_t)m * 4;
    float acc = bias[c];
    acc += xr[0] * w[c] + xr[1] * w[256 + c] + xr[2] * w[512 + c] + xr[3] * w[768 + c];
    out[idx] = gelu_tanh(acc);
}

// ---------------------------------------------------------------------------
// Repack head weights [H, C, VD] -> [C, H*VD] row-major
// ---------------------------------------------------------------------------
__global__ void k_repack_w(const float* __restrict__ w_hcv, float* __restrict__ wrep) {
    int idx = blockIdx.x * blockDim.x + threadIdx.x;   // 65536
    int k = idx >> 8;
    int n = idx & 255;
    int h = n >> 5;
    int v = n & 31;
    wrep[idx] = w_hcv[(size_t)h * CC * VD + (size_t)k * VD + v];
}

// ---------------------------------------------------------------------------
// Global (unmasked) attention rows: att = softmax(-md*scale) per (h,q) row.
// ---------------------------------------------------------------------------
__global__ void k_att_global(const float* __restrict__ md,
                             const float* __restrict__ r,
                             float* __restrict__ att,
                             int Nq, int Nk) {
    extern __shared__ float sm[];
    float* row = sm;
    float* red = sm + Nk;
    int rowid = blockIdx.x;
    int h = rowid / Nq;
    float scale = head_scale(r[h]);
    const float* src = md + (size_t)rowid * Nk;
    float* dst = att + (size_t)rowid * Nk;
    int tid = threadIdx.x;

    float mn = 3.402823466e+38f;
    for (int k = tid; k < Nk; k += 256) {
        float v = src[k] * scale;
        row[k] = v;
        mn = fminf(mn, v);
    }
    red[tid] = mn; __syncthreads();
    for (int s = 128; s > 0; s >>= 1) {
        if (tid < s) red[tid] = fminf(red[tid], red[tid + s]);
        __syncthreads();
    }
    mn = red[0];
    __syncthreads();

    float sum = 0.0f;
    for (int k = tid; k < Nk; k += 256) {
        float e = expf(mn - row[k]);   // logits = -sd; max logit = -mn
        row[k] = e;
        sum += e;
    }
    red[tid] = sum; __syncthreads();
    for (int s = 128; s > 0; s >>= 1) {
        if (tid < s) red[tid] += red[tid + s];
        __syncthreads();
    }
    float inv = 1.0f / red[0];
    for (int k = tid; k < Nk; k += 256) dst[k] = row[k] * inv;
}

// ---------------------------------------------------------------------------
// Masked attention rows (locality=30, Nk=1024)
// ---------------------------------------------------------------------------
__global__ void k_att_masked(const float* __restrict__ md,
                             const float* __restrict__ r,
                             float* __restrict__ att) {
    __shared__ float vals[NL];
    __shared__ float srt[NL];
    __shared__ float red[256];
    int rowid = blockIdx.x;           // h*NL + q
    int h = rowid / NL;
    float scale = head_scale(r[h]);
    const float* src = md + (size_t)rowid * NL;
    float* dst = att + (size_t)rowid * NL;
    int tid = threadIdx.x;

    for (int k = tid; k < NL; k += 256) {
        float v = src[k] * scale;
        vals[k] = v;
        srt[k]  = v;
    }
    __syncthreads();

    // Bitonic sort ascending (1024 elements)
    for (int k = 2; k <= NL; k <<= 1) {
        for (int j = k >> 1; j > 0; j >>= 1) {
            for (int i = tid; i < NL; i += 256) {
                int ixj = i ^ j;
                if (ixj > i) {
                    bool up = ((i & k) == 0);
                    float a = srt[i], b = srt[ixj];
                    if ((a > b) == up) { srt[i] = b; srt[ixj] = a; }
                }
            }
            __syncthreads();
        }
    }

    // percentile(30) over n=1024: idx = 0.3*1023 = 306.9
    float a306 = srt[306], a307 = srt[307];
    float thr = a306 + 0.9f * (a307 - a306);
    float mn  = srt[0];

    float sum = 0.0f;
    for (int k = tid; k < NL; k += 256) {
        float v = vals[k];
        float e = (v <= thr) ? expf(mn - v) : 0.0f;
        vals[k] = e;
        sum += e;
    }
    red[tid] = sum; __syncthreads();
    for (int s = 128; s > 0; s >>= 1) {
        if (tid < s) red[tid] += red[tid + s];
        __syncthreads();
    }
    float inv = 1.0f / red[0];
    for (int k = tid; k < NL; k += 256) dst[k] = vals[k] * inv;
}

// ---------------------------------------------------------------------------
// TF32 tensor-core GEMM: C = epilogue(A[M,K] @ B[K,256]).
// Block tile 128x128x16, 256 threads, 8 warps (2 along M x 4 along N),
// warp tile 64x32 via m16n8k8 (4x4 MMA tiles). Double-buffered DYNAMIC smem
// with fragments pre-arranged in MMA lane order (tf32-converted on store).
//   grid: (M/128, 2, nHeads); blockIdx.z offsets A/B by per-head strides.
//   flags: bit0 = gelu, bit1 = add addbuf[m*256+n]
//   store_mode: 0 plain; 1 att-apply scatter; 2 value scatter.
// Requires M%128==0, K%16==0 (true at all call sites).
// ---------------------------------------------------------------------------
__global__ void __launch_bounds__(256, 2)
k_gemm_tc(const float* __restrict__ A, const float* __restrict__ B,
          float* __restrict__ C, int M, int K,
          size_t strideA_h, size_t strideB_h,
          const float* __restrict__ bias, const float* __restrict__ addbuf,
          int flags, int store_mode, int s_param)
{
    const int h = blockIdx.z;
    A += (size_t)h * strideA_h;
    B += (size_t)h * strideB_h;

    // Dynamic smem (49,664 B total — above the 48KB static limit, so we use
    // extern __shared__ + MaxDynamicSharedMemorySize opt-in on the host).
    // A fragments: [buf][kstep][mtile(8)][lane*4 + reg]  (uint tf32 bits)
    // B fragments: [buf][kstep][ntile(16)][lane*2 + reg] pad 66 to break
    // store-phase bank degeneracy.
    extern __shared__ uint32_t dynsm[];
    typedef uint32_t AsT[2][8][128];
    typedef uint32_t BsT[2][16][66];
    AsT* As = (AsT*)dynsm;                          // [2] double buffer
    BsT* Bs = (BsT*)(dynsm + GEMM_SMEM_WORDS_A);    // [2] double buffer

    const int tid  = threadIdx.x;
    const int lane = tid & 31;
    const int warp = tid >> 5;
    const int wm   = warp & 1;       // 0..1  (M)
    const int wn   = warp >> 1;      // 0..3  (N)
    const int m0   = blockIdx.x * 128;
    const int n0   = blockIdx.y * 128;

    float acc[4][4][4];
#pragma unroll
    for (int mi = 0; mi < 4; mi++)
#pragma unroll
        for (int ni = 0; ni < 4; ni++)
#pragma unroll
            for (int q = 0; q < 4; q++) acc[mi][ni][q] = 0.0f;

    float4 ra[2], rb[2];
    const int KT = K >> 4;

    auto FETCH = [&](int kt) {
        int k0 = kt * 16;
#pragma unroll
        for (int p = 0; p < 2; p++) {
            int q = tid + p * 256;            // 0..511
            int m = q >> 2, kq = q & 3;       // A tile row / float4 within row
            ra[p] = *(const float4*)(A + (size_t)(m0 + m) * K + k0 + kq * 4);
        }
#pragma unroll
        for (int p = 0; p < 2; p++) {
            int q = tid + p * 256;
            int n4 = q & 31, k = q >> 5;      // B tile: k-row, float4 along n
            rb[p] = *(const float4*)(B + (size_t)(k0 + k) * 256 + n0 + n4 * 4);
        }
    };

    auto STORE = [&](int buf) {
#pragma unroll
        for (int p = 0; p < 2; p++) {
            int q = tid + p * 256;
            int m = q >> 2, kq = q & 3;
            int r = m & 15, mt = m >> 4;
            int kk = kq >> 1, cf = kq & 1;        // k-step, col>=4 flag
            int reg = ((r >> 3) & 1) + (cf << 1); // a-frag register index
            int lb = (r & 7) * 4;                 // lane base
            uint32_t* d = &As[buf][kk][mt][0];
            d[(lb + 0) * 4 + reg] = f2tf32(ra[p].x);
            d[(lb + 1) * 4 + reg] = f2tf32(ra[p].y);
            d[(lb + 2) * 4 + reg] = f2tf32(ra[p].z);
            d[(lb + 3) * 4 + reg] = f2tf32(ra[p].w);
        }
#pragma unroll
        for (int p = 0; p < 2; p++) {
            int q = tid + p * 256;
            int n4 = q & 31, k = q >> 5;
            int kk = k >> 3, kr = k & 7;
            int reg = kr >> 2, klo = kr & 3;
            float v[4] = {rb[p].x, rb[p].y, rb[p].z, rb[p].w};
#pragma unroll
            for (int ci = 0; ci < 4; ci++) {
                int n = n4 * 4 + ci;
                int nt = n >> 3;
                int ln = (n & 7) * 4 + klo;
                Bs[buf][kk][nt][ln * 2 + reg] = f2tf32(v[ci]);
            }
        }
    };

    auto COMPUTE = [&](int buf) {
#pragma unroll
        for (int kk = 0; kk < 2; kk++) {
            uint32_t af[4][4];
            uint32_t bf[4][2];
#pragma unroll
            for (int mi = 0; mi < 4; mi++) {
                uint4 t = *(const uint4*)&As[buf][kk][wm * 4 + mi][lane * 4];
                af[mi][0] = t.x; af[mi][1] = t.y; af[mi][2] = t.z; af[mi][3] = t.w;
            }
#pragma unroll
            for (int ni = 0; ni < 4; ni++) {
                uint2 t = *(const uint2*)&Bs[buf][kk][wn * 4 + ni][lane * 2];
                bf[ni][0] = t.x; bf[ni][1] = t.y;
            }
#pragma unroll
            for (int mi = 0; mi < 4; mi++)
#pragma unroll
                for (int ni = 0; ni < 4; ni++)
                    mma_tf32(acc[mi][ni], af[mi], bf[ni]);
        }
    };

    FETCH(0);
    STORE(0);
    for (int kt = 0; kt < KT; kt++) {
        __syncthreads();
        int buf = kt & 1;
        if (kt + 1 < KT) FETCH(kt + 1);
        COMPUTE(buf);
        if (kt + 1 < KT) STORE(buf ^ 1);
    }

    // ---- epilogue ----
    const int gr = lane >> 2;
    const int gc = lane & 3;
#pragma unroll
    for (int mi = 0; mi < 4; mi++) {
#pragma unroll
        for (int hf = 0; hf < 2; hf++) {
            int m = m0 + wm * 64 + mi * 16 + gr + hf * 8;
#pragma unroll
            for (int ni = 0; ni < 4; ni++) {
                int n = n0 + wn * 32 + ni * 8 + gc * 2;
                float v0 = acc[mi][ni][hf * 2 + 0];
                float v1 = acc[mi][ni][hf * 2 + 1];
                if (bias) { v0 += bias[n]; v1 += bias[n + 1]; }
                if (flags & 2) {
                    v0 += addbuf[(size_t)m * 256 + n];
                    v1 += addbuf[(size_t)m * 256 + n + 1];
                }
                if (flags & 1) { v0 = gelu_tanh(v0); v1 = gelu_tanh(v1); }
                size_t idx;
                if (store_mode == 0) {
                    idx = (size_t)m * 256 + n;
                } else if (store_mode == 1) {
                    int bb = n >> 5, vv = n & 31;
                    idx = (size_t)bb * s_param * 256 + (size_t)m * 256 + (size_t)h * 32 + vv;
                } else {
                    int bb = m / s_param, kp = m % s_param;
                    int hh = n >> 5, vv = n & 31;
                    idx = (size_t)hh * s_param * 256 + (size_t)kp * 256 + (size_t)bb * 32 + vv;
                }
                *(float2*)(C + idx) = make_float2(v0, v1);
            }
        }
    }
}

// ---------------------------------------------------------------------------
// Final projection: out[m] = A[m,:] . w[:,0] + b[0]   (one warp per row)
// ---------------------------------------------------------------------------
__global__ void k_fc2(const float* __restrict__ A, const float* __restrict__ w,
                      const float* __restrict__ b, float* __restrict__ out, int M) {
    int gwarp = (blockIdx.x * blockDim.x + threadIdx.x) >> 5;
    int lane = threadIdx.x & 31;
    if (gwarp >= M) return;
    const float* a = A + (size_t)gwarp * 256;
    float s = 0.0f;
#pragma unroll
    for (int k = lane; k < 256; k += 32) s += a[k] * w[k];
#pragma unroll
    for (int off = 16; off > 0; off >>= 1)
        s += __shfl_down_sync(0xFFFFFFFFu, s, off);
    if (lane == 0) out[gwarp] = s + b[0];
}

// ---------------------------------------------------------------------------
// Host orchestration
// ---------------------------------------------------------------------------
extern "C" void kernel_launch(void* const* d_in, const int* in_sizes, int n_in,
                              void* d_out, int out_size) {
    (void)in_sizes; (void)n_in; (void)out_size;

    const float* x       = (const float*)d_in[0];
    const float* md_down = (const float*)d_in[1];
    const float* md_p[2] = {(const float*)d_in[2], (const float*)d_in[3]};
    const float* md_up   = (const float*)d_in[4];
    const float* en_w    = (const float*)d_in[5];
    const float* en_b    = (const float*)d_in[6];
    const float* down_r  = (const float*)d_in[7];
    const float* down_w  = (const float*)d_in[8];
    const float* pa_r[2] = {(const float*)d_in[9],  (const float*)d_in[17]};
    const float* pa_w[2] = {(const float*)d_in[10], (const float*)d_in[18]};
    const float* f1w[2]  = {(const float*)d_in[11], (const float*)d_in[19]};
    const float* f1b[2]  = {(const float*)d_in[12], (const float*)d_in[20]};
    const float* f2w[2]  = {(const float*)d_in[13], (const float*)d_in[21]};
    const float* f2b[2]  = {(const float*)d_in[14], (const float*)d_in[22]};
    const float* rw[2]   = {(const float*)d_in[15], (const float*)d_in[23]};
    const float* rb[2]   = {(const float*)d_in[16], (const float*)d_in[24]};
    const float* up_r    = (const float*)d_in[25];
    const float* up_w    = (const float*)d_in[26];
    const float* de1w    = (const float*)d_in[27];
    const float* de1b    = (const float*)d_in[28];
    const float* de2w    = (const float*)d_in[29];
    const float* de2b    = (const float*)d_in[30];

    // Opt-in for >48KB dynamic smem (deterministic, capture-safe host call).
    cudaFuncSetAttribute(k_gemm_tc, cudaFuncAttributeMaxDynamicSharedMemorySize,
                         GEMM_SMEM_BYTES);

    float* S = nullptr;
    cudaGetSymbolAddress((void**)&S, g_scratch);
    float* att     = S + OFF_ATT;
    float* attp    = S + OFF_ATT_P;
    float* val     = S + OFF_VAL;
    float* hfull   = S + OFF_HFULL;
    float* tmpfull = S + OFF_TMPFULL;
    float* lat0    = S + OFF_LAT0;
    float* lat1    = S + OFF_LAT1;
    float* lat2    = S + OFF_LAT2;
    float* wrep    = S + OFF_WREP;

    // ---- encoder ----
    k_encoder<<<(BB * NF * CC) / 256, 256>>>(x, en_w, en_b, hfull);

    // ---- down attention (global, Nq=1024, Nk=4096) ----
    k_repack_w<<<256, 256>>>(down_w, wrep);
    k_gemm_tc<<<dim3(BB * NF / 128, 2, 1), 256, GEMM_SMEM_BYTES>>>(
        hfull, wrep, val, BB * NF, 256, 0, 0, nullptr, nullptr, 0, 2, NF);
    k_att_global<<<HH * NL, 256, (NF + 256) * sizeof(float)>>>(md_down, down_r, att, NL, NF);
    k_gemm_tc<<<dim3(NL / 128, 2, HH), 256, GEMM_SMEM_BYTES>>>(
        att, val, lat0, NL, NF, (size_t)NL * NF, (size_t)NF * CC,
        nullptr, nullptr, 1, 1, NL);

    // ---- two latent PiT blocks (masked attention, locality=30) ----
    float* hin  = lat0;
    float* bufP = lat1;
    float* bufT = lat2;
    for (int i = 0; i < 2; i++) {
        k_repack_w<<<256, 256>>>(pa_w[i], wrep);
        k_gemm_tc<<<dim3(BB * NL / 128, 2, 1), 256, GEMM_SMEM_BYTES>>>(
            hin, wrep, val, BB * NL, 256, 0, 0, nullptr, nullptr, 0, 2, NL);
        k_att_masked<<<HH * NL, 256>>>(md_p[i], pa_r[i], attp);
        k_gemm_tc<<<dim3(NL / 128, 2, HH), 256, GEMM_SMEM_BYTES>>>(
            attp, val, bufP, NL, NL, (size_t)NL * NL, (size_t)NL * CC,
            nullptr, nullptr, 1, 1, NL);
        // mlp fc1 (gelu)
        k_gemm_tc<<<dim3(BB * NL / 128, 2, 1), 256, GEMM_SMEM_BYTES>>>(
            bufP, f1w[i], bufT, BB * NL, 256, 0, 0, f1b[i], nullptr, 1, 0, 0);
        // mlp fc2 (no act) -> overwrite bufP
        k_gemm_tc<<<dim3(BB * NL / 128, 2, 1), 256, GEMM_SMEM_BYTES>>>(
            bufT, f2w[i], bufP, BB * NL, 256, 0, 0, f2b[i], nullptr, 0, 0, 0);
        // h = gelu(mlp + hin@rw + rb) -> bufT
        k_gemm_tc<<<dim3(BB * NL / 128, 2, 1), 256, GEMM_SMEM_BYTES>>>(
            hin, rw[i], bufT, BB * NL, 256, 0, 0, rb[i], bufP, 3, 0, 0);
        float* nh = bufT; bufT = hin; hin = nh;
    }

    // ---- up attention (global, Nq=4096, Nk=1024) ----
    k_repack_w<<<256, 256>>>(up_w, wrep);
    k_gemm_tc<<<dim3(BB * NL / 128, 2, 1), 256, GEMM_SMEM_BYTES>>>(
        hin, wrep, val, BB * NL, 256, 0, 0, nullptr, nullptr, 0, 2, NL);
    k_att_global<<<HH * NF, 256, (NL + 256) * sizeof(float)>>>(md_up, up_r, att, NF, NL);
    k_gemm_tc<<<dim3(NF / 128, 2, HH), 256, GEMM_SMEM_BYTES>>>(
        att, val, hfull, NF, NL, (size_t)NF * NL, (size_t)NL * CC,
        nullptr, nullptr, 1, 1, NF);

    // ---- decoder ----
    k_gemm_tc<<<dim3(BB * NF / 128, 2, 1), 256, GEMM_SMEM_BYTES>>>(
        hfull, de1w, tmpfull, BB * NF, 256, 0, 0, de1b, nullptr, 1, 0, 0);
    k_fc2<<<(BB * NF * 32) / 256, 256>>>(tmpfull, de2w, de2b, (float*)d_out, BB * NF);
}